// round 16
// baseline (speedup 1.0000x reference)
#include <cuda_runtime.h>
#include <cuda_bf16.h>
#include <cstdint>

// Problem constants
#define SEQn 256
#define Bn   64
#define Hn   512
#define Ln   4
#define NJ   16       // output columns per block
#define NBC  32       // blocks per layer
#define NTHR 512      // 16 warps; warp w owns k-slice [w*16,w*16+16) of each chunk
#define KCH  256      // k per staged chunk (2 inp + 2 h chunks)

// ---- SMEM byte map ----
// W tiles: [16 rows][1024 k] bf16, row stride 2064 B (516 words %32==4 -> CF).
// A tiles: [2 dbuf][hi|lo][64 rows][256 k] bf16, row stride 528 B (132 %32==4).
// RED (split-K partials, 16 warps) overlays the A region (dead when RED used).
#define WROWB  2064
#define SM_WHI 0
#define SM_WLO (16 * WROWB)              // 33,024
#define SM_A   (2 * 16 * WROWB)          // 66,048
#define AROWB  528
#define ATILEB (64 * AROWB)              // 33,792
#define ABUF   (2 * ATILEB)              // 67,584 (hi+lo)
#define SM_RED SM_A                      // overlay (16*64*20*4 = 81,920 B fits)
#define REDW   20
#define SMEM_BYTES (SM_A + 2 * ABUF)     // 201,216 B

// ---- PTX helpers (baseline sm_80+) ----
#define LDSM4(r0, r1, r2, r3, addr) \
    asm volatile("ldmatrix.sync.aligned.m8n8.x4.shared.b16 {%0,%1,%2,%3}, [%4];" \
                 : "=r"(r0), "=r"(r1), "=r"(r2), "=r"(r3) : "r"(addr))

#define MMA_BF16(d, a, b0, b1) \
    asm volatile("mma.sync.aligned.m16n8k16.row.col.f32.bf16.bf16.f32 " \
                 "{%0,%1,%2,%3}, {%4,%5,%6,%7}, {%8,%9}, {%0,%1,%2,%3};" \
                 : "+f"(d[0]), "+f"(d[1]), "+f"(d[2]), "+f"(d[3]) \
                 : "r"(a[0]), "r"(a[1]), "r"(a[2]), "r"(a[3]), "r"(b0), "r"(b1))

__device__ __forceinline__ uint32_t smem_u32(const void* p) {
    uint32_t a;
    asm("{ .reg .u64 t; cvta.to.shared.u64 t, %1; cvt.u32.u64 %0, t; }"
        : "=r"(a) : "l"(p));
    return a;
}
__device__ __forceinline__ uint4 ld_cg_u4(const void* p) {
    uint4 v;
    asm volatile("ld.global.cg.v4.u32 {%0,%1,%2,%3}, [%4];"
                 : "=r"(v.x), "=r"(v.y), "=r"(v.z), "=r"(v.w) : "l"(p));
    return v;
}
__device__ __forceinline__ void st_cg_f2(float* p, float a, float b) {
    asm volatile("st.global.cg.v2.f32 [%0], {%1,%2};"
                 :: "l"(p), "f"(a), "f"(b) : "memory");
}
__device__ __forceinline__ void st_cg_u32(void* p, uint32_t a) {
    asm volatile("st.global.cg.u32 [%0], %1;" :: "l"(p), "r"(a) : "memory");
}

// Persistent scratch: bf16 hi/lo copies of states and x (write-once per cell).
__device__ __nv_bfloat16 g_shi[(size_t)SEQn * Ln * Bn * Hn];
__device__ __nv_bfloat16 g_slo[(size_t)SEQn * Ln * Bn * Hn];
__device__ __nv_bfloat16 g_xhi[(size_t)SEQn * Bn * Hn];
__device__ __nv_bfloat16 g_xlo[(size_t)SEQn * Bn * Hn];

__device__ int g_cnt[Ln * SEQn];

// Prologue: zero counters + x -> bf16 hi/lo scratch (one kernel).
__global__ void prologue_kernel(const float* __restrict__ x) {
    if (blockIdx.x == 0) {
        for (int i = threadIdx.x; i < Ln * SEQn; i += blockDim.x) g_cnt[i] = 0;
    }
    const int n4 = SEQn * Bn * Hn / 4;
    for (int i = blockIdx.x * blockDim.x + threadIdx.x; i < n4;
         i += gridDim.x * blockDim.x) {
        float4 v = ((const float4*)x)[i];
        __nv_bfloat162 h01 = __floats2bfloat162_rn(v.x, v.y);
        __nv_bfloat162 h23 = __floats2bfloat162_rn(v.z, v.w);
        __nv_bfloat162 l01 = __floats2bfloat162_rn(v.x - __bfloat162float(h01.x),
                                                   v.y - __bfloat162float(h01.y));
        __nv_bfloat162 l23 = __floats2bfloat162_rn(v.z - __bfloat162float(h23.x),
                                                   v.w - __bfloat162float(h23.y));
        ((uint2*)g_xhi)[i] = make_uint2(*(uint32_t*)&h01, *(uint32_t*)&h23);
        ((uint2*)g_xlo)[i] = make_uint2(*(uint32_t*)&l01, *(uint32_t*)&l23);
    }
}

__global__ __launch_bounds__(NTHR, 1)
void rnn_kernel(const float* __restrict__ x,
                const float* __restrict__ w_ih,
                const float* __restrict__ b_ih,
                const float* __restrict__ w_hh,
                const float* __restrict__ b_hh,
                float* __restrict__ out)
{
    const int layer = blockIdx.x >> 5;
    const int cb    = blockIdx.x & (NBC - 1);
    const int j0    = cb * NJ;
    const int tid   = threadIdx.x;
    const int w     = tid >> 5;       // 16 warps: k-slice w*16 of each chunk
    const int lane  = tid & 31;

    extern __shared__ __align__(16) char smem[];
    const uint32_t sb = smem_u32(smem);

    float* outputs = out;
    float* states  = out + SEQn * Bn * Hn;

    // ---- One-time: W = [Wih | Whh] (16 rows x 1024 k) -> bf16 hi/lo tiles ----
    for (int u = 0; u < 32; ++u) {
        int i = u * NTHR + tid;
        int j = i >> 10, k = i & 1023;
        float v = (k < 512)
            ? w_ih[(size_t)(layer * Hn + j0 + j) * Hn + k]
            : w_hh[(size_t)(layer * Hn + j0 + j) * Hn + (k - 512)];
        __nv_bfloat16 hi = __float2bfloat16(v);
        __nv_bfloat16 lo = __float2bfloat16(v - __bfloat162float(hi));
        *(__nv_bfloat16*)(smem + SM_WHI + j * WROWB + k * 2) = hi;
        *(__nv_bfloat16*)(smem + SM_WLO + j * WROWB + k * 2) = lo;
    }
    float bias0, bias1;
    {
        int jb = layer * Hn + j0 + (tid & 7) * 2;
        bias0 = b_ih[jb + 0] + b_hh[jb + 0];
        bias1 = b_ih[jb + 1] + b_hh[jb + 1];
    }
    __syncthreads();

    // ldmatrix lane-address components (validated in R14/R15)
    const int tq = lane >> 3, rq = lane & 7;
    const int a_m_off = (tq & 1) * 8 + rq;
    const int a_k_off = (tq >> 1) * 8;
    const int b_n     = (tq >> 1) * 8 + rq;
    const int b_k_off = (tq & 1) * 8;

    for (int t = 0; t < SEQn; ++t) {
        // ---- Dependency wait (identical protocol to prior passing rounds) ----
        if (tid == 0) {
            volatile int* vc = g_cnt;
            if (t > 0) {
                int s = 0;
                while (vc[layer * SEQn + t - 1] < NBC) {
                    __nanosleep(20); if (++s > 2000000) break;
                }
            }
            if (layer > 0) {
                int s = 0;
                while (vc[(layer - 1) * SEQn + t] < NBC) {
                    __nanosleep(20); if (++s > 2000000) break;
                }
            }
            __threadfence();
        }
        __syncthreads();

        // bf16 hi/lo activation sources (scratch; always .cg)
        const __nv_bfloat16* inpHi = (layer == 0)
            ? (g_xhi + (size_t)t * Bn * Hn)
            : (g_shi + (size_t)(t * Ln + (layer - 1)) * Bn * Hn);
        const __nv_bfloat16* inpLo = (layer == 0)
            ? (g_xlo + (size_t)t * Bn * Hn)
            : (g_slo + (size_t)(t * Ln + (layer - 1)) * Bn * Hn);
        const __nv_bfloat16* hHi = g_shi + (size_t)((t - 1) * Ln + layer) * Bn * Hn;
        const __nv_bfloat16* hLo = g_slo + (size_t)((t - 1) * Ln + layer) * Bn * Hn;
        const int ncc = (t == 0) ? 2 : 4;   // chunks 0,1 = inp; 2,3 = h

        float D[4][2][4];
        #pragma unroll
        for (int mt = 0; mt < 4; ++mt)
            #pragma unroll
            for (int nt = 0; nt < 2; ++nt)
                #pragma unroll
                for (int q = 0; q < 4; ++q) D[mt][nt][q] = 0.f;

        // Stage chunk 0 (pure copy: LDG.cg bf16 -> STS). 8 uint4/thread.
        uint4 pf[8];
        #pragma unroll
        for (int u = 0; u < 8; ++u) {
            int f = (u & 3) * NTHR + tid;      // row = f>>5, c4 = f&31 (16B units)
            const __nv_bfloat16* src = (u < 4) ? inpHi : inpLo;
            pf[u] = ld_cg_u4(src + (f >> 5) * Hn + (f & 31) * 8);
        }
        #pragma unroll
        for (int u = 0; u < 8; ++u) {
            int f = (u & 3) * NTHR + tid;
            char* dst = smem + SM_A + ((u < 4) ? 0 : ATILEB)
                        + (f >> 5) * AROWB + (f & 31) * 16;
            *(uint4*)dst = pf[u];
        }
        __syncthreads();

        for (int c = 0; c < ncc; ++c) {
            const int buf = c & 1;

            if (c + 1 < ncc) {     // next-chunk LDGs first (hidden under mma)
                const __nv_bfloat16* sH = ((c + 1) < 2) ? inpHi : hHi;
                const __nv_bfloat16* sL = ((c + 1) < 2) ? inpLo : hLo;
                int koff = ((c + 1) & 1) * KCH;
                #pragma unroll
                for (int u = 0; u < 8; ++u) {
                    int f = (u & 3) * NTHR + tid;
                    const __nv_bfloat16* src = (u < 4) ? sH : sL;
                    pf[u] = ld_cg_u4(src + (f >> 5) * Hn + koff + (f & 31) * 8);
                }
            }

            // ---- Tensor compute: warp k-slice = c*256 + w*16 (one k16 step) ----
            {
                int kg = c * KCH + w * 16;
                uint32_t bAddrH = sb + SM_WHI + b_n * WROWB + (kg + b_k_off) * 2;
                uint32_t bAddrL = bAddrH + (SM_WLO - SM_WHI);
                uint32_t bh[4], bl[4];
                LDSM4(bh[0], bh[1], bh[2], bh[3], bAddrH);
                LDSM4(bl[0], bl[1], bl[2], bl[3], bAddrL);

                uint32_t aBase = sb + SM_A + buf * ABUF + a_m_off * AROWB
                                 + (w * 16 + a_k_off) * 2;
                #pragma unroll
                for (int mt = 0; mt < 4; ++mt) {
                    uint32_t ah[4];
                    LDSM4(ah[0], ah[1], ah[2], ah[3], aBase + mt * 16 * AROWB);
                    MMA_BF16(D[mt][0], ah, bh[0], bh[1]);
                    MMA_BF16(D[mt][1], ah, bh[2], bh[3]);
                    MMA_BF16(D[mt][0], ah, bl[0], bl[1]);
                    MMA_BF16(D[mt][1], ah, bl[2], bl[3]);
                }
                #pragma unroll
                for (int mt = 0; mt < 4; ++mt) {
                    uint32_t al[4];
                    LDSM4(al[0], al[1], al[2], al[3],
                          aBase + ATILEB + mt * 16 * AROWB);
                    MMA_BF16(D[mt][0], al, bh[0], bh[1]);
                    MMA_BF16(D[mt][1], al, bh[2], bh[3]);
                }
            }

            if (c + 1 < ncc) {     // stage next chunk into other buffer
                char* abase = smem + SM_A + ((c + 1) & 1) * ABUF;
                #pragma unroll
                for (int u = 0; u < 8; ++u) {
                    int f = (u & 3) * NTHR + tid;
                    char* dst = abase + ((u < 4) ? 0 : ATILEB)
                                + (f >> 5) * AROWB + (f & 31) * 16;
                    *(uint4*)dst = pf[u];
                }
            }
            __syncthreads();
        }

        // ---- Split-K reduction across 16 warps (RED overlays dead A region) ----
        {
            float* red = (float*)(smem + SM_RED) + w * (64 * REDW);
            #pragma unroll
            for (int mt = 0; mt < 4; ++mt)
                #pragma unroll
                for (int nt = 0; nt < 2; ++nt) {
                    int m = mt * 16 + (lane >> 2);
                    int n = nt * 8 + 2 * (lane & 3);
                    *(float2*)(red + m * REDW + n) =
                        make_float2(D[mt][nt][0], D[mt][nt][1]);
                    *(float2*)(red + (m + 8) * REDW + n) =
                        make_float2(D[mt][nt][2], D[mt][nt][3]);
                }
        }
        __syncthreads();

        // Finalize 2 outputs/thread: b = tid>>3, j = j0 + (tid&7)*2 .. +1
        {
            int b  = tid >> 3;
            int jq = (tid & 7) * 2;
            float a0 = bias0, a1 = bias1;
            const float* redb = (const float*)(smem + SM_RED) + b * REDW + jq;
            #pragma unroll
            for (int w2 = 0; w2 < 16; ++w2) {
                float2 p = *(const float2*)(redb + w2 * (64 * REDW));
                a0 += p.x; a1 += p.y;
            }
            float v0 = tanhf(a0), v1 = tanhf(a1);

            size_t sidx = ((size_t)(t * Ln + layer) * Bn + b) * Hn + j0 + jq;
            st_cg_f2(states + sidx, v0, v1);
            if (layer == Ln - 1) {
                float* op = outputs + ((size_t)t * Bn + b) * Hn + j0 + jq;
                st_cg_f2(op, v0, v1);
            }
            // Publish bf16 hi/lo for downstream consumers (our 2 values)
            __nv_bfloat162 h01 = __floats2bfloat162_rn(v0, v1);
            __nv_bfloat162 l01 = __floats2bfloat162_rn(
                v0 - __bfloat162float(h01.x), v1 - __bfloat162float(h01.y));
            st_cg_u32(g_shi + sidx, *(uint32_t*)&h01);
            st_cg_u32(g_slo + sidx, *(uint32_t*)&l01);
        }

        // Publish step completion (release)
        __threadfence();
        __syncthreads();
        if (tid == 0) atomicAdd(&g_cnt[layer * SEQn + t], 1);
    }
}

extern "C" void kernel_launch(void* const* d_in, const int* in_sizes, int n_in,
                              void* d_out, int out_size) {
    const float* x    = (const float*)d_in[0];   // [SEQ,B,H]
    const float* w_ih = (const float*)d_in[1];   // [L,H,H]
    const float* b_ih = (const float*)d_in[2];   // [L,H]
    const float* w_hh = (const float*)d_in[3];   // [L,H,H]
    const float* b_hh = (const float*)d_in[4];   // [L,H]
    float* out = (float*)d_out;                  // outputs ++ states

    cudaFuncSetAttribute(rnn_kernel,
                         cudaFuncAttributeMaxDynamicSharedMemorySize, SMEM_BYTES);

    prologue_kernel<<<1024, 256>>>(x);
    rnn_kernel<<<Ln * NBC, NTHR, SMEM_BYTES>>>(x, w_ih, b_ih, w_hh, b_hh, out);
}